// round 8
// baseline (speedup 1.0000x reference)
#include <cuda_runtime.h>
#include <cstdint>
#include <math.h>

#define S_LEN 128
#define B_SZ  128
#define E_DIM 64
#define H_DIM 8
#define V_SZ  30000
#define T_OUT 12
#define NSAMP (S_LEN * B_SZ)
#define FULLM 0xffffffffu
#define CH    16        // steps per pipeline chunk
#define NCH   (S_LEN / CH)

// ======================================================================
// Compile-time numpy legacy RandomState(1234) replica -> fixed gate list
// ======================================================================
struct CtOps { int k[30]; int a[30]; int b[30]; double th[30]; };

__host__ __device__ constexpr void ct_twist(uint32_t* mt) {
    for (int i = 0; i < 624; i++) {
        uint32_t y = (mt[i] & 0x80000000u) | (mt[(i + 1) % 624] & 0x7fffffffu);
        mt[i] = mt[(i + 397) % 624] ^ (y >> 1) ^ ((y & 1u) ? 0x9908b0dfu : 0u);
    }
}
__host__ __device__ constexpr uint32_t ct_next(uint32_t* mt, int& mti) {
    if (mti >= 624) { ct_twist(mt); mti = 0; }
    uint32_t y = mt[mti++];
    y ^= y >> 11;
    y ^= (y << 7) & 0x9d2c5680u;
    y ^= (y << 15) & 0xefc60000u;
    y ^= y >> 18;
    return y;
}
__host__ __device__ constexpr uint32_t ct_ri(uint32_t* mt, int& mti, uint32_t n) {
    uint32_t rng = n - 1u, mask = rng;
    mask |= mask >> 1; mask |= mask >> 2; mask |= mask >> 4;
    mask |= mask >> 8; mask |= mask >> 16;
    uint32_t v = ct_next(mt, mti) & mask;
    while (v > rng) v = ct_next(mt, mti) & mask;
    return v;
}
__host__ __device__ constexpr double ct_rs(uint32_t* mt, int& mti) {
    uint32_t a = ct_next(mt, mti) >> 5, b = ct_next(mt, mti) >> 6;
    return (a * 67108864.0 + b) * (1.0 / 9007199254740992.0);
}
__host__ __device__ constexpr CtOps ct_build() {
    uint32_t mt[624] = {};
    mt[0] = 1234u;
    for (int i = 1; i < 624; i++)
        mt[i] = 1812433253u * (mt[i - 1] ^ (mt[i - 1] >> 30)) + (uint32_t)i;
    int mti = 624;
    CtOps R{};
    const double TWO_PI = 6.283185307179586476925286766559;
    for (int t = 0; t < 30; t++) {
        uint32_t kind = ct_ri(mt, mti, 4u);
        if (kind == 3u) {
            int c = (int)ct_ri(mt, mti, 8u);
            int tt = (int)ct_ri(mt, mti, 7u);
            if (tt >= c) tt += 1;
            R.k[t] = 3; R.a[t] = c; R.b[t] = tt; R.th[t] = 0.0;
        } else {
            int w = (int)ct_ri(mt, mti, 8u);
            R.k[t] = (int)kind; R.a[t] = w; R.b[t] = 0;
            R.th[t] = TWO_PI * ct_rs(mt, mti);
        }
    }
    return R;
}
static constexpr CtOps OPS = ct_build();

__host__ __device__ constexpr double ct_cos(double x) {
    double t = 1.0, sum = 1.0;
    for (int k = 1; k <= 25; k++) { t *= -x * x / ((2.0 * k - 1.0) * (2.0 * k)); sum += t; }
    return sum;
}
__host__ __device__ constexpr double ct_sin(double x) {
    double t = x, sum = x;
    for (int k = 1; k <= 25; k++) { t *= -x * x / ((2.0 * k) * (2.0 * k + 1.0)); sum += t; }
    return sum;
}

// wire -> amp-bit permutation: 3 most shfl-expensive wires in register bits
struct Perm { int p[8]; };
__host__ __device__ constexpr Perm build_perm() {
    int score[8] = {};
    for (int t = 0; t < 30; t++) {
        if (OPS.k[t] == 3) { score[OPS.b[t]] += 2; score[OPS.a[t]] += 1; }
        else if (OPS.k[t] == 0 || OPS.k[t] == 1) score[OPS.a[t]] += 2;
    }
    Perm P{};
    bool used[8] = {};
    for (int r = 0; r < 3; r++) {
        int best = -1, bs = -1;
        for (int w = 0; w < 8; w++)
            if (!used[w] && score[w] > bs) { bs = score[w]; best = w; }
        used[best] = true;
        P.p[best] = r;
    }
    int nb = 3;
    for (int w = 0; w < 8; w++)
        if (!used[w]) P.p[w] = nb++;
    return P;
}
static constexpr Perm PB = build_perm();
template<int W> struct PBit { static constexpr int p = PB.p[W]; };

template<int T> struct OpK {
    static constexpr int   kind = OPS.k[T];
    static constexpr int   pa   = PB.p[OPS.a[T]];
    static constexpr int   pb   = PB.p[OPS.b[T]];
    static constexpr float thf  = (float)OPS.th[T];
    static constexpr float hf   = thf * 0.5f;
    static constexpr float c    = (float)ct_cos((double)hf);
    static constexpr float s    = (float)ct_sin((double)hf);
};

// ======================================================================
// packed f32x2 helpers (two samples per 64-bit register)
// ======================================================================
typedef unsigned long long u64;

__device__ __forceinline__ u64 f2fma(u64 a, u64 b, u64 c) {
    u64 d;
    asm("fma.rn.f32x2 %0, %1, %2, %3;" : "=l"(d) : "l"(a), "l"(b), "l"(c));
    return d;
}
__device__ __forceinline__ u64 f2mul(u64 a, u64 b) {
    u64 d;
    asm("mul.rn.f32x2 %0, %1, %2;" : "=l"(d) : "l"(a), "l"(b));
    return d;
}
__device__ __forceinline__ u64 f2add(u64 a, u64 b) {
    u64 d;
    asm("add.rn.f32x2 %0, %1, %2;" : "=l"(d) : "l"(a), "l"(b));
    return d;
}
__device__ __forceinline__ u64 f2sub(u64 a, u64 b) {
    u64 d;
    asm("sub.rn.f32x2 %0, %1, %2;" : "=l"(d) : "l"(a), "l"(b));
    return d;
}
__device__ __forceinline__ u64 f2pack(float lo, float hi) {
    u64 d;
    asm("mov.b64 %0, {%1, %2};" : "=l"(d) : "f"(lo), "f"(hi));
    return d;
}
__device__ __forceinline__ u64 f2bcast(float x) { return f2pack(x, x); }
__device__ __forceinline__ void f2unpack(u64 v, float& lo, float& hi) {
    asm("mov.b64 {%0, %1}, %2;" : "=f"(lo), "=f"(hi) : "l"(v));
}
__device__ __forceinline__ u64 f2neg(u64 v) { return v ^ 0x8000000080000000ULL; }
__device__ __forceinline__ u64 shfl64(u64 v, int m) {
    return __shfl_xor_sync(FULLM, v, m);
}

// ======================================================================
// packed qfc gate primitives
// ======================================================================
template<int P>
__device__ __forceinline__ void rx_loc_p(u64 re[8], u64 im[8], u64 cc, u64 ss, u64 ns) {
#pragma unroll
    for (int e = 0; e < 8; e++) {
        if (e & (1 << P)) continue;
        int o = e | (1 << P);
        u64 a0r = re[e], a0i = im[e], a1r = re[o], a1i = im[o];
        re[e] = f2fma(cc, a0r, f2mul(ss, a1i));
        im[e] = f2fma(cc, a0i, f2mul(ns, a1r));
        re[o] = f2fma(cc, a1r, f2mul(ss, a0i));
        im[o] = f2fma(cc, a1i, f2mul(ns, a0r));
    }
}
template<int P>
__device__ __forceinline__ void ry_loc_p(u64 re[8], u64 im[8], u64 cc, u64 ss, u64 ns) {
#pragma unroll
    for (int e = 0; e < 8; e++) {
        if (e & (1 << P)) continue;
        int o = e | (1 << P);
        u64 a0r = re[e], a0i = im[e], a1r = re[o], a1i = im[o];
        re[e] = f2fma(cc, a0r, f2mul(ns, a1r));
        im[e] = f2fma(cc, a0i, f2mul(ns, a1i));
        re[o] = f2fma(cc, a1r, f2mul(ss, a0r));
        im[o] = f2fma(cc, a1i, f2mul(ss, a0i));
    }
}
__device__ __forceinline__ void rx_lane_p(u64 re[8], u64 im[8], u64 cc, u64 ss, u64 ns, int m) {
#pragma unroll
    for (int j = 0; j < 8; j++) {
        u64 sr = shfl64(re[j], m);
        u64 si = shfl64(im[j], m);
        re[j] = f2fma(cc, re[j], f2mul(ss, si));
        im[j] = f2fma(cc, im[j], f2mul(ns, sr));
    }
}
__device__ __forceinline__ void ry_lane_p(u64 re[8], u64 im[8], u64 cc, u64 tt, int m) {
#pragma unroll
    for (int j = 0; j < 8; j++) {
        u64 sr = shfl64(re[j], m);
        u64 si = shfl64(im[j], m);
        re[j] = f2fma(cc, re[j], f2mul(tt, sr));
        im[j] = f2fma(cc, im[j], f2mul(tt, si));
    }
}

template<int T>
__device__ __forceinline__ void apply_one_p(u64 re[8], u64 im[8], int lane) {
    constexpr int kind = OpK<T>::kind;
    if constexpr (kind == 3) {
        constexpr int pc = OpK<T>::pa;
        constexpr int pt = OpK<T>::pb;
        if constexpr (pt >= 3) {
            constexpr int m = 1 << (pt - 3);
            if constexpr (pc >= 3) {
                int ctrl = (lane >> (pc - 3)) & 1;
#pragma unroll
                for (int j = 0; j < 8; j++) {
                    u64 sr = shfl64(re[j], m);
                    u64 si = shfl64(im[j], m);
                    re[j] = ctrl ? sr : re[j];
                    im[j] = ctrl ? si : im[j];
                }
            } else {
#pragma unroll
                for (int j = 0; j < 8; j++) {
                    if ((j >> pc) & 1) {
                        re[j] = shfl64(re[j], m);
                        im[j] = shfl64(im[j], m);
                    }
                }
            }
        } else {
            constexpr int tm = 1 << pt;
            if constexpr (pc >= 3) {
                if ((lane >> (pc - 3)) & 1) {
#pragma unroll
                    for (int e = 0; e < 8; e++) {
                        if (e & tm) continue;
                        int o = e | tm;
                        u64 tr = re[e]; re[e] = re[o]; re[o] = tr;
                        u64 ti = im[e]; im[e] = im[o]; im[o] = ti;
                    }
                }
            } else {
#pragma unroll
                for (int e = 0; e < 8; e++) {
                    if ((e & tm) || !((e >> pc) & 1)) continue;
                    int o = e | tm;
                    u64 tr = re[e]; re[e] = re[o]; re[o] = tr;
                    u64 ti = im[e]; im[e] = im[o]; im[o] = ti;
                }
            }
        }
    } else if constexpr (kind == 2) {      // rz
        constexpr int p = OpK<T>::pa;
        u64 cc = f2bcast(OpK<T>::c);
        u64 sp = f2bcast(OpK<T>::s);
        u64 sn = f2bcast(-OpK<T>::s);
        if constexpr (p >= 3) {
            int bit = (lane >> (p - 3)) & 1;
            u64 tp = bit ? sn : sp;
            u64 tn = bit ? sp : sn;
#pragma unroll
            for (int j = 0; j < 8; j++) {
                u64 r = re[j], i = im[j];
                re[j] = f2fma(tp, i, f2mul(cc, r));
                im[j] = f2fma(tn, r, f2mul(cc, i));
            }
        } else {
#pragma unroll
            for (int j = 0; j < 8; j++) {
                u64 tp = ((j >> p) & 1) ? sn : sp;
                u64 tn = ((j >> p) & 1) ? sp : sn;
                u64 r = re[j], i = im[j];
                re[j] = f2fma(tp, i, f2mul(cc, r));
                im[j] = f2fma(tn, r, f2mul(cc, i));
            }
        }
    } else if constexpr (kind == 0) {      // rx
        constexpr int p = OpK<T>::pa;
        u64 cc = f2bcast(OpK<T>::c);
        u64 ss = f2bcast(OpK<T>::s);
        u64 ns = f2bcast(-OpK<T>::s);
        if constexpr (p >= 3)      rx_lane_p(re, im, cc, ss, ns, 1 << (p - 3));
        else if constexpr (p == 0) rx_loc_p<0>(re, im, cc, ss, ns);
        else if constexpr (p == 1) rx_loc_p<1>(re, im, cc, ss, ns);
        else                       rx_loc_p<2>(re, im, cc, ss, ns);
    } else {                                // ry
        constexpr int p = OpK<T>::pa;
        u64 cc = f2bcast(OpK<T>::c);
        if constexpr (p >= 3) {
            int bit = (lane >> (p - 3)) & 1;
            u64 tt = f2bcast(bit ? OpK<T>::s : -OpK<T>::s);
            ry_lane_p(re, im, cc, tt, 1 << (p - 3));
        } else {
            u64 ss = f2bcast(OpK<T>::s);
            u64 ns = f2bcast(-OpK<T>::s);
            if constexpr (p == 0) ry_loc_p<0>(re, im, cc, ss, ns);
            else if constexpr (p == 1) ry_loc_p<1>(re, im, cc, ss, ns);
            else                       ry_loc_p<2>(re, im, cc, ss, ns);
        }
    }
}
template<int T>
__device__ __forceinline__ void apply_seq_p(u64 re[8], u64 im[8], int lane) {
    if constexpr (T < 30) {
        apply_one_p<T>(re, im, lane);
        apply_seq_p<T + 1>(re, im, lane);
    }
}

template<int W>
__device__ __forceinline__ void init_lane_factor_p(u64& fr, const u64 cs[8],
                                                   const u64 sn[8], int lane) {
    if constexpr (W < 8) {
        constexpr int p = PBit<W>::p;
        if constexpr (p >= 3) {
            int bit = (lane >> (p - 3)) & 1;
            fr = f2mul(fr, bit ? sn[W] : cs[W]);
        }
        init_lane_factor_p<W + 1>(fr, cs, sn, lane);
    }
}
template<int J, int W>
__device__ __forceinline__ void reg_factor_acc_p(u64& g, const u64 cs[8], const u64 sn[8]) {
    if constexpr (W < 8) {
        constexpr int p = PBit<W>::p;
        if constexpr (p < 3) {
            if constexpr (((J >> p) & 1) != 0) g = f2mul(g, sn[W]);
            else                               g = f2mul(g, cs[W]);
        }
        reg_factor_acc_p<J, W + 1>(g, cs, sn);
    }
}
template<int J>
__device__ __forceinline__ void init_amps_p(u64 re[8], u64 im[8], u64 fr,
                                            const u64 cs[8], const u64 sn[8]) {
    if constexpr (J < 8) {
        u64 g = fr;
        reg_factor_acc_p<J, 0>(g, cs, sn);
        re[J] = g;
        im[J] = 0ULL;
        init_amps_p<J + 1>(re, im, fr, cs, sn);
    }
}

template<int W>
__device__ __forceinline__ void final_rx_p(u64 re[8], u64 im[8],
                                           const float* pcs, const float* psn, int lane) {
    if constexpr (W < 8) {
        constexpr int p = PBit<W>::p;
        u64 cc = f2bcast(pcs[W]);
        u64 ss = f2bcast(psn[W]);
        u64 ns = f2neg(ss);
        if constexpr (p >= 3)      rx_lane_p(re, im, cc, ss, ns, 1 << (p - 3));
        else if constexpr (p == 0) rx_loc_p<0>(re, im, cc, ss, ns);
        else if constexpr (p == 1) rx_loc_p<1>(re, im, cc, ss, ns);
        else                       rx_loc_p<2>(re, im, cc, ss, ns);
        final_rx_p<W + 1>(re, im, pcs, psn, lane);
    }
}

template<int W>
__device__ __forceinline__ void measure_w_p(u64 zp[8], const u64 pj[8],
                                            u64 tot, int lane) {
    if constexpr (W < 8) {
        constexpr int p = PBit<W>::p;
        if constexpr (p >= 3) {
            zp[W] = ((lane >> (p - 3)) & 1) ? f2neg(tot) : tot;
        } else {
            u64 pos = 0ULL, neg = 0ULL;
#pragma unroll
            for (int j = 0; j < 8; j++) {
                if ((j >> p) & 1) neg = f2add(neg, pj[j]);
                else              pos = f2add(pos, pj[j]);
            }
            zp[W] = f2sub(pos, neg);
        }
        measure_w_p<W + 1>(zp, pj, tot, lane);
    }
}

// one packed QFC sim for a pair of samples
__device__ __forceinline__ void qfc_sim_pair(const float* __restrict__ hA,
                                             const float* __restrict__ hB,
                                             const float* __restrict__ pcs,
                                             const float* __restrict__ psn,
                                             const float WhH[8], float bH,
                                             float* __restrict__ outA,
                                             float* __restrict__ outB, int lane) {
    u64 re[8], im[8];
    {
        u64 cs[8], sn[8];
#pragma unroll
        for (int w = 0; w < 8; w++) {
            float cA, sA, cB, sB;
            __sincosf(0.5f * hA[w], &sA, &cA);
            __sincosf(0.5f * hB[w], &sB, &cB);
            cs[w] = f2pack(cA, cB);
            sn[w] = f2pack(sA, sB);
        }
        u64 fr = f2bcast(1.f);
        init_lane_factor_p<0>(fr, cs, sn, lane);
        init_amps_p<0>(re, im, fr, cs, sn);
    }
    apply_seq_p<0>(re, im, lane);
    final_rx_p<0>(re, im, pcs, psn, lane);

    u64 pj[8], tot = 0ULL;
#pragma unroll
    for (int j = 0; j < 8; j++) {
        pj[j] = f2fma(re[j], re[j], f2mul(im[j], im[j]));
        tot = f2add(tot, pj[j]);
    }
    u64 zp[8];
    measure_w_p<0>(zp, pj, tot, lane);
#pragma unroll
    for (int off = 16; off >= 1; off >>= 1) {
#pragma unroll
        for (int w = 0; w < 8; w++) zp[w] = f2add(zp[w], shfl64(zp[w], off));
    }

    float zA[8], zB[8];
#pragma unroll
    for (int w = 0; w < 8; w++) f2unpack(zp[w], zA[w], zB[w]);

    float lA = __int_as_float(0xff800000), lB = lA;
    if (lane < T_OUT) {
        lA = bH; lB = bH;
#pragma unroll
        for (int h = 0; h < 8; h++) {
            lA = fmaf(zA[h], WhH[h], lA);
            lB = fmaf(zB[h], WhH[h], lB);
        }
    }
    float mA = lA, mB = lB;
#pragma unroll
    for (int off = 16; off >= 1; off >>= 1) {
        mA = fmaxf(mA, __shfl_xor_sync(FULLM, mA, off));
        mB = fmaxf(mB, __shfl_xor_sync(FULLM, mB, off));
    }
    float eA = (lane < T_OUT) ? __expf(lA - mA) : 0.f;
    float eB = (lane < T_OUT) ? __expf(lB - mB) : 0.f;
#pragma unroll
    for (int off = 16; off >= 1; off >>= 1) {
        eA += __shfl_xor_sync(FULLM, eA, off);
        eB += __shfl_xor_sync(FULLM, eB, off);
    }
    if (lane < T_OUT) {
        outA[lane] = lA - mA - __logf(eA);
        outB[lane] = lB - mB - __logf(eB);
    }
}

__device__ __forceinline__ float tanhfast(float x) {
    float y;
    asm("tanh.approx.f32 %0, %1;" : "=f"(y) : "f"(x));
    return y;
}

// ======================================================================
// fused kernel: 1 block per batch element b. 14 warps:
//   warp 0      : LSTM chunk c           (zbuf -> hbuf)
//   warps 1..8  : packed QFC pair chunk c-1 (hbuf -> out), 2 samples each
//   warps 9..13 : embed projection c+1   (gmem -> zbuf)
// ======================================================================
__global__ void __launch_bounds__(448) k_fused(
    const float* __restrict__ emb, const float* __restrict__ Win,
    const float* __restrict__ b_in, const float* __restrict__ phi,
    const float* __restrict__ Wout, const float* __restrict__ b_out,
    const float* __restrict__ phiq, const float* __restrict__ Whead,
    const float* __restrict__ b_head, const long long* __restrict__ sent,
    float* __restrict__ out)
{
    __shared__ float sW[32 * 76];
    __shared__ float zbuf[2][CH][32];
    __shared__ float hbuf[2][CH][8];
    __shared__ float pcs[8], psn[8];
    __shared__ int   s_is64;

    int tid = threadIdx.x;
    int wid = tid >> 5;
    int lane = tid & 31;
    int b = blockIdx.x;

    for (int i = tid; i < 32 * 72; i += 448) {
        int r = i / 72, f = i - r * 72;
        sW[r * 76 + f] = Win[i];
    }
    if (tid < 8) {
        float c, s;
        __sincosf(0.5f * phiq[tid], &s, &c);
        pcs[tid] = c; psn[tid] = s;
    }
    if (tid == 0) {
        int cnt = 0;
        for (int i = 0; i < 8; i++) {
            long long v = sent[i];
            cnt += (v >= 0 && v < V_SZ);
        }
        s_is64 = (cnt >= 5);
    }
    __syncthreads();
    bool is64 = (s_is64 != 0);

    // role-persistent state
    float Wh[8], Wo[8], bphi = 0.f, bo = 0.f, hn = 0.f, cst = 0.f;
    int hh = 0, basem = 0; bool isg = false;
    if (wid == 0) {
#pragma unroll
        for (int j = 0; j < 8; j++) Wh[j] = sW[lane * 76 + 64 + j];
#pragma unroll
        for (int j = 0; j < 8; j++) Wo[j] = Wout[lane * 8 + j];
        bphi = b_in[lane] + phi[lane];
        bo = b_out[lane];
        hh = lane & 7; basem = lane & 24; isg = (basem == 16);
    }
    float WhH[8]; float bH = 0.f;
    if (wid >= 1 && wid <= 8) {
        if (lane < T_OUT) {
#pragma unroll
            for (int h = 0; h < 8; h++) WhH[h] = Whead[lane * 8 + h];
            bH = b_head[lane];
        } else {
#pragma unroll
            for (int h = 0; h < 8; h++) WhH[h] = 0.f;
        }
    }

    for (int i = 0; i < NCH + 2; i++) {
        if (wid >= 9) {
            int ce = i;
            if (ce < NCH) {
                for (int t = wid - 9; t < CH; t += 5) {
                    int s = ce * CH + t;
                    long long tok = is64 ? sent[s * B_SZ + b]
                                         : (long long)(((const int*)sent)[s * B_SZ + b]);
                    const float4* er = reinterpret_cast<const float4*>(emb + (size_t)tok * E_DIM);
                    const float4* wr = reinterpret_cast<const float4*>(&sW[lane * 76]);
                    float a0 = 0.f, a1 = 0.f, a2 = 0.f, a3 = 0.f;
#pragma unroll
                    for (int k = 0; k < 16; k++) {
                        float4 e4 = er[k];
                        float4 w4 = wr[k];
                        a0 = fmaf(e4.x, w4.x, a0); a1 = fmaf(e4.y, w4.y, a1);
                        a2 = fmaf(e4.z, w4.z, a2); a3 = fmaf(e4.w, w4.w, a3);
                    }
                    zbuf[ce & 1][t][lane] = (a0 + a1) + (a2 + a3);
                }
            }
        } else if (wid == 0) {
            int cl = i - 1;
            if (cl >= 0 && cl < NCH) {
                float zt[CH];
#pragma unroll
                for (int t = 0; t < CH; t++) zt[t] = zbuf[cl & 1][t][lane];
#pragma unroll 1
                for (int t = 0; t < CH; t++) {
                    float za = zt[t] + bphi, zb = 0.f;
#pragma unroll
                    for (int j = 0; j < 4; j++) {
                        za = fmaf(Wh[j],     __shfl_sync(FULLM, hn, j),     za);
                        zb = fmaf(Wh[j + 4], __shfl_sync(FULLM, hn, j + 4), zb);
                    }
                    float myc = __cosf(za + zb);
                    float cj[8];
#pragma unroll
                    for (int j = 0; j < 8; j++) cj[j] = __shfl_sync(FULLM, myc, basem + j);
                    float tt = Wo[7];
#pragma unroll
                    for (int q = 6; q >= 0; q--) tt = fmaf(cj[q + 1], tt, Wo[q]);
                    float pre = fmaf(cj[0], tt, bo);
                    float arg = isg ? pre : 0.5f * pre;
                    float ta = tanhfast(arg);
                    float a = isg ? ta : fmaf(0.5f, ta, 0.5f);
                    float vf = __shfl_sync(FULLM, a, hh);
                    float vi = __shfl_sync(FULLM, a, 8 + hh);
                    float vg = __shfl_sync(FULLM, a, 16 + hh);
                    float vo = __shfl_sync(FULLM, a, 24 + hh);
                    cst = fmaf(vf, cst, vi * vg);
                    hn = vo * tanhfast(cst);
                    if (lane < 8) hbuf[cl & 1][t][lane] = hn;
                }
            }
        } else {
            int cq = i - 2;
            if (cq >= 0) {
                int t0 = 2 * (wid - 1);
                int n0 = b * S_LEN + cq * CH + t0;
                qfc_sim_pair(&hbuf[cq & 1][t0][0], &hbuf[cq & 1][t0 + 1][0],
                             pcs, psn, WhH, bH,
                             out + (size_t)n0 * T_OUT,
                             out + (size_t)(n0 + 1) * T_OUT, lane);
            }
        }
        __syncthreads();
    }
}

// ======================================================================
extern "C" void kernel_launch(void* const* d_in, const int* in_sizes, int n_in,
                              void* d_out, int out_size) {
    const float* emb     = (const float*)d_in[0];
    const float* Win     = (const float*)d_in[1];
    const float* b_in    = (const float*)d_in[2];
    const float* phi     = (const float*)d_in[3];
    const float* Wout    = (const float*)d_in[4];
    const float* b_out   = (const float*)d_in[5];
    const float* phiq    = (const float*)d_in[6];
    const float* Whead   = (const float*)d_in[7];
    const float* b_head  = (const float*)d_in[8];
    const long long* sent = (const long long*)d_in[9];
    float* out = (float*)d_out;

    k_fused<<<B_SZ, 448>>>(emb, Win, b_in, phi, Wout, b_out,
                           phiq, Whead, b_head, sent, out);
}